// round 4
// baseline (speedup 1.0000x reference)
#include <cuda_runtime.h>
#include <mma.h>
using namespace nvcuda;

#define NB 4
#define NS 2048
#define IND 1024
#define NH 16
#define HD 64
#define OUTD 1024

__device__ float g_q[(size_t)NB * NH * NS * HD];
__device__ float g_k[(size_t)NB * NH * NS * HD];
__device__ float g_v[(size_t)NB * NH * NS * HD];

__device__ __forceinline__ void cp_async16(void* smem_dst, const void* gsrc) {
  unsigned s = (unsigned)__cvta_generic_to_shared(smem_dst);
  asm volatile("cp.async.cg.shared.global [%0], [%1], 16;\n" ::"r"(s), "l"(gsrc));
}
__device__ __forceinline__ void cp_commit() {
  asm volatile("cp.async.commit_group;\n");
}
template <int N>
__device__ __forceinline__ void cp_wait() {
  asm volatile("cp.async.wait_group %0;\n" ::"n"(N));
}

// ---------------------------------------------------------------------------
// Projection: C[8192,1024] = X @ W, TF32 WMMA, 128x64 block tile, K-chunk 32,
// 2-stage cp.async pipeline. 16 warps (4x4), warp tile 32x16.
// ---------------------------------------------------------------------------
#define P_LDA 40
#define P_LDB 72

__global__ __launch_bounds__(512) void proj_kernel(
    const float* __restrict__ Xq, const float* __restrict__ Xk,
    const float* __restrict__ Xv, const float* __restrict__ Wq,
    const float* __restrict__ Wk, const float* __restrict__ Wv) {
  const float* X;
  const float* W;
  float* O;
  if (blockIdx.z == 0) { X = Xq; W = Wq; O = g_q; }
  else if (blockIdx.z == 1) { X = Xk; W = Wk; O = g_k; }
  else { X = Xv; W = Wv; O = g_v; }

  extern __shared__ float psm[];
  float* sA = psm;                    // 2 x 128 x 40
  float* sB = psm + 2 * 128 * P_LDA;  // 2 x 32 x 72

  const int tid = threadIdx.x;
  const int wid = tid >> 5;
  const int warp_m = wid >> 2;  // 0..3 -> 32-row slab
  const int warp_n = wid & 3;   // 0..3 -> 16-col slab
  const int bm = blockIdx.y;
  const int bn = blockIdx.x;  // head index

  wmma::fragment<wmma::accumulator, 16, 16, 8, float> c[2];
#pragma unroll
  for (int i = 0; i < 2; i++) wmma::fill_fragment(c[i], 0.0f);

  auto issue = [&](int kb, int st) {
    float* dA = sA + st * 128 * P_LDA;
    float* dB = sB + st * 32 * P_LDB;
#pragma unroll
    for (int i = 0; i < 2; i++) {
      int t = tid + i * 512;
      int r = t >> 3, c4 = t & 7;
      cp_async16(&dA[r * P_LDA + c4 * 4],
                 &X[(size_t)(bm * 128 + r) * IND + kb + c4 * 4]);
    }
    {
      int r = tid >> 4, c4 = tid & 15;
      cp_async16(&dB[r * P_LDB + c4 * 4],
                 &W[(size_t)(kb + r) * OUTD + bn * 64 + c4 * 4]);
    }
  };

  issue(0, 0);
  cp_commit();

  for (int ci = 0; ci < IND / 32; ci++) {
    const int st = ci & 1;
    if (ci + 1 < IND / 32) issue((ci + 1) * 32, (ci + 1) & 1);
    cp_commit();
    cp_wait<1>();
    __syncthreads();

    const float* cA = sA + st * 128 * P_LDA;
    const float* cB = sB + st * 32 * P_LDB;
#pragma unroll
    for (int kk = 0; kk < 32; kk += 8) {
      wmma::fragment<wmma::matrix_a, 16, 16, 8, wmma::precision::tf32,
                     wmma::row_major> a[2];
      wmma::fragment<wmma::matrix_b, 16, 16, 8, wmma::precision::tf32,
                     wmma::row_major> b;
#pragma unroll
      for (int i = 0; i < 2; i++) {
        wmma::load_matrix_sync(a[i], &cA[(warp_m * 32 + i * 16) * P_LDA + kk],
                               P_LDA);
#pragma unroll
        for (int e = 0; e < a[i].num_elements; e++)
          a[i].x[e] = wmma::__float_to_tf32(a[i].x[e]);
      }
      wmma::load_matrix_sync(b, &cB[kk * P_LDB + warp_n * 16], P_LDB);
#pragma unroll
      for (int e = 0; e < b.num_elements; e++)
        b.x[e] = wmma::__float_to_tf32(b.x[e]);
#pragma unroll
      for (int i = 0; i < 2; i++) wmma::mma_sync(c[i], a[i], b, c[i]);
    }
    __syncthreads();
  }

  const int b = (bm * 128) / NS;
  const int srow = (bm * 128) % NS;
  float* obase = O + ((size_t)(b * NH + bn) * NS + srow) * HD;
#pragma unroll
  for (int i = 0; i < 2; i++)
    wmma::store_matrix_sync(
        obase + (size_t)(warp_m * 32 + i * 16) * HD + warp_n * 16, c[i], HD,
        wmma::mem_row_major);
}

// ---------------------------------------------------------------------------
// Attention: one block per (bh, 128-query tile). 16 warps (4x4), warp tile
// 32x16. Deferred-normalization softmax, exp on accumulator registers,
// register row-sum partials, K/V 2-stage cp.async pipeline.
// ---------------------------------------------------------------------------
#define BQ 128
#define BK 64
#define LDP 72

__global__ __launch_bounds__(512) void attn_kernel(float* __restrict__ out) {
  extern __shared__ float smem[];
  float* sQ = smem;                 // 128 x 72 (pre-scaled)
  float* sS = sQ + BQ * LDP;        // 128 x 72
  float* sK = sS + BQ * LDP;        // 2 x 64 x 72
  float* sV = sK + 2 * BK * LDP;    // 2 x 64 x 72
  float* rs = sV + 2 * BK * LDP;    // 128

  const int tid = threadIdx.x;
  const int wid = tid >> 5;
  const int warp_m = wid >> 2;  // 0..3
  const int warp_n = wid & 3;   // 0..3
  const int bh = blockIdx.y;
  const int qt = blockIdx.x;

  const float* Qg = g_q + ((size_t)bh * NS + qt * BQ) * HD;
  const float* Kg = g_k + (size_t)bh * NS * HD;
  const float* Vg = g_v + (size_t)bh * NS * HD;

#pragma unroll
  for (int i = 0; i < 4; i++) {
    int t = tid + i * 512;
    int r = t >> 4, c4 = t & 15;
    float4 v = *(const float4*)&Qg[(size_t)r * HD + c4 * 4];
    v.x *= 0.125f; v.y *= 0.125f; v.z *= 0.125f; v.w *= 0.125f;
    *(float4*)&sQ[r * LDP + c4 * 4] = v;
  }

  auto issue = [&](int kb, int st) {
    float* dK = sK + st * BK * LDP;
    float* dV = sV + st * BK * LDP;
#pragma unroll
    for (int i = 0; i < 2; i++) {
      int t = tid + i * 512;
      int r = t >> 4, c4 = t & 15;
      cp_async16(&dK[r * LDP + c4 * 4], &Kg[(size_t)(kb + r) * HD + c4 * 4]);
      cp_async16(&dV[r * LDP + c4 * 4], &Vg[(size_t)(kb + r) * HD + c4 * 4]);
    }
  };

  issue(0, 0);
  cp_commit();

  wmma::fragment<wmma::accumulator, 16, 16, 8, float> o_acc[2];
#pragma unroll
  for (int i = 0; i < 2; i++) wmma::fill_fragment(o_acc[i], 0.0f);

  const int rrow = tid >> 2;         // row owned for row-sum (4 thr/row)
  const int rq = (tid & 3) * 16;     // 16-col quarter
  float rsum = 0.0f;

  for (int ci = 0; ci < NS / BK; ci++) {
    const int st = ci & 1;
    if (ci + 1 < NS / BK) issue((ci + 1) * BK, (ci + 1) & 1);
    cp_commit();
    cp_wait<1>();
    __syncthreads();

    const float* cK = sK + st * BK * LDP;
    const float* cV = sV + st * BK * LDP;

    // S = Q * K^T over d=64.
    wmma::fragment<wmma::accumulator, 16, 16, 8, float> s_acc[2];
#pragma unroll
    for (int i = 0; i < 2; i++) wmma::fill_fragment(s_acc[i], 0.0f);

#pragma unroll
    for (int kk = 0; kk < HD; kk += 8) {
      wmma::fragment<wmma::matrix_a, 16, 16, 8, wmma::precision::tf32,
                     wmma::row_major> a[2];
      wmma::fragment<wmma::matrix_b, 16, 16, 8, wmma::precision::tf32,
                     wmma::col_major> bfr;
#pragma unroll
      for (int i = 0; i < 2; i++) {
        wmma::load_matrix_sync(a[i], &sQ[(warp_m * 32 + i * 16) * LDP + kk],
                               LDP);
#pragma unroll
        for (int e = 0; e < a[i].num_elements; e++)
          a[i].x[e] = wmma::__float_to_tf32(a[i].x[e]);
      }
      wmma::load_matrix_sync(bfr, &cK[(warp_n * 16) * LDP + kk], LDP);
#pragma unroll
      for (int e = 0; e < bfr.num_elements; e++)
        bfr.x[e] = wmma::__float_to_tf32(bfr.x[e]);
#pragma unroll
      for (int i = 0; i < 2; i++)
        wmma::mma_sync(s_acc[i], a[i], bfr, s_acc[i]);
    }

    // exp in registers, stage probs.
#pragma unroll
    for (int i = 0; i < 2; i++) {
#pragma unroll
      for (int e = 0; e < s_acc[i].num_elements; e++)
        s_acc[i].x[e] = __expf(s_acc[i].x[e]);
      wmma::store_matrix_sync(
          &sS[(warp_m * 32 + i * 16) * LDP + warp_n * 16], s_acc[i], LDP,
          wmma::mem_row_major);
    }
    __syncthreads();

    // Row-sum partial: 4 threads/row, rotated 16-col walk, register acc.
    {
      const float* p = &sS[rrow * LDP + rq];
      float s = 0.0f;
#pragma unroll
      for (int j = 0; j < 16; j++) s += p[(rrow + j) & 15];
      rsum += s;
    }

    // O += P * V over 64 keys.
#pragma unroll
    for (int kk = 0; kk < BK; kk += 8) {
      wmma::fragment<wmma::matrix_a, 16, 16, 8, wmma::precision::tf32,
                     wmma::row_major> a[2];
      wmma::fragment<wmma::matrix_b, 16, 16, 8, wmma::precision::tf32,
                     wmma::row_major> bfr;
#pragma unroll
      for (int i = 0; i < 2; i++) {
        wmma::load_matrix_sync(a[i], &sS[(warp_m * 32 + i * 16) * LDP + kk],
                               LDP);
#pragma unroll
        for (int e = 0; e < a[i].num_elements; e++)
          a[i].x[e] = wmma::__float_to_tf32(a[i].x[e]);
      }
      wmma::load_matrix_sync(bfr, &cV[kk * LDP + warp_n * 16], LDP);
#pragma unroll
      for (int e = 0; e < bfr.num_elements; e++)
        bfr.x[e] = wmma::__float_to_tf32(bfr.x[e]);
#pragma unroll
      for (int i = 0; i < 2; i++)
        wmma::mma_sync(o_acc[i], a[i], bfr, o_acc[i]);
    }
    __syncthreads();  // protect sS and K/V stages before next iteration
  }

  // Finalize row sums (reduce 4 partials per row) and stage O.
  {
    float tot = rsum;
    tot += __shfl_xor_sync(0xffffffffu, tot, 1);
    tot += __shfl_xor_sync(0xffffffffu, tot, 2);
    if ((tid & 3) == 0) rs[rrow] = tot;
  }
#pragma unroll
  for (int i = 0; i < 2; i++)
    wmma::store_matrix_sync(&sS[(warp_m * 32 + i * 16) * LDP + warp_n * 16],
                            o_acc[i], LDP, wmma::mem_row_major);
  __syncthreads();

  const int b = bh / NH;
  const int h = bh % NH;
  const int s0 = qt * BQ;
#pragma unroll
  for (int i = 0; i < 4; i++) {
    int t = tid + i * 512;
    int r = t >> 4, c4 = t & 15;
    float4 v = *(float4*)&sS[r * LDP + c4 * 4];
    float inv = 1.0f / rs[r];
    v.x *= inv; v.y *= inv; v.z *= inv; v.w *= inv;
    *(float4*)&out[((size_t)(b * NS + s0 + r)) * OUTD + h * HD + c4 * 4] = v;
  }
}

// ---------------------------------------------------------------------------
extern "C" void kernel_launch(void* const* d_in, const int* in_sizes, int n_in,
                              void* d_out, int out_size) {
  const float* query = (const float*)d_in[0];
  const float* key   = (const float*)d_in[1];
  const float* value = (const float*)d_in[2];
  const float* WQ    = (const float*)d_in[3];
  const float* WK    = (const float*)d_in[4];
  const float* WV    = (const float*)d_in[5];
  float* out = (float*)d_out;

  const int proj_smem = (2 * 128 * P_LDA + 2 * 32 * P_LDB) * 4;
  const int attn_smem =
      (BQ * LDP + BQ * LDP + 2 * BK * LDP + 2 * BK * LDP + BQ) * 4;
  cudaFuncSetAttribute(proj_kernel, cudaFuncAttributeMaxDynamicSharedMemorySize,
                       proj_smem);
  cudaFuncSetAttribute(attn_kernel, cudaFuncAttributeMaxDynamicSharedMemorySize,
                       attn_smem);

  dim3 pgrid(OUTD / 64, (NB * NS) / 128, 3);
  proj_kernel<<<pgrid, 512, proj_smem>>>(query, key, value, WQ, WK, WV);

  dim3 agrid(NS / BQ, NB * NH);
  attn_kernel<<<agrid, 512, attn_smem>>>(out);
}